// round 1
// baseline (speedup 1.0000x reference)
#include <cuda_runtime.h>
#include <math.h>

#define B_   2
#define S_   1024
#define D_   1024
#define H_   16
#define DH_  64
#define FF_  4096
#define V_   32000
#define L_   4
#define PAD_ 3
#define CTX_ 1025

// ---------------- scratch (static device globals; no runtime alloc) -------
__device__ float g_x  [B_*S_*D_];
__device__ float g_xn [B_*S_*D_];
__device__ float g_q  [B_*S_*D_];
__device__ float g_k  [B_*S_*D_];
__device__ float g_v  [B_*S_*D_];
__device__ float g_o  [B_*S_*D_];
__device__ float g_tmp[B_*S_*D_];
__device__ float g_rel[S_*D_];
__device__ float g_r  [S_*D_];
__device__ float g_ff [B_*S_*FF_];
__device__ float g_aw [(size_t)B_*H_*S_*S_];   // scores then attn weights (128 MB)

// ---------------- helpers --------------------------------------------------
__device__ __forceinline__ float gelu_t(float x){
    return 0.5f*x*(1.0f + tanhf(0.7978845608028654f*(x + 0.044715f*x*x*x)));
}

// ---------------- embedding ------------------------------------------------
__global__ void embed_kernel(const int* __restrict__ text, const float* __restrict__ emb){
    int idx = blockIdx.x*256 + threadIdx.x;        // over B*S*D/4
    int d4  = idx & (D_/4 - 1);
    int bs  = idx >> 8;                             // /(D/4)
    int s   = bs & (S_-1);
    int b   = bs >> 10;
    int tok = text[b*CTX_ + s];
    ((float4*)g_x)[idx] = ((const float4*)(emb + (size_t)tok*D_))[d4];
}

// ---------------- sinusoidal relative positions ----------------------------
__global__ void rel_kernel(){
    int idx = blockIdx.x*256 + threadIdx.x;        // over S*(D/2)
    int j = idx & 511;
    int s = idx >> 9;
    float pos  = (float)(S_-1-s);
    float invf = powf(10000.0f, -(float)(2*j)/(float)D_);
    float a = pos*invf;
    g_rel[s*D_ + j]       = sinf(a);
    g_rel[s*D_ + j + 512] = cosf(a);
}

// ---------------- layernorm (one block per row, 256 thr, D=1024) -----------
__global__ void ln_kernel(const float* __restrict__ in, float* __restrict__ out,
                          const float* __restrict__ gam, const float* __restrict__ bet){
    int row = blockIdx.x;
    int t = threadIdx.x;
    const float4* x4 = (const float4*)(in + (size_t)row*D_);
    float4 v = x4[t];
    float s  = v.x+v.y+v.z+v.w;
    float s2 = v.x*v.x+v.y*v.y+v.z*v.z+v.w*v.w;
    #pragma unroll
    for (int o=16;o;o>>=1){ s += __shfl_xor_sync(0xffffffffu,s,o); s2 += __shfl_xor_sync(0xffffffffu,s2,o); }
    __shared__ float shs[8], shs2[8], bc[2];
    int w = t>>5, lane = t&31;
    if (!lane){ shs[w]=s; shs2[w]=s2; }
    __syncthreads();
    if (t==0){
        float ts=0.f, ts2=0.f;
        #pragma unroll
        for (int i=0;i<8;i++){ ts+=shs[i]; ts2+=shs2[i]; }
        float m   = ts*(1.0f/(float)D_);
        float var = ts2*(1.0f/(float)D_) - m*m;
        bc[0]=m; bc[1]=rsqrtf(var + 1e-5f);
    }
    __syncthreads();
    float m = bc[0], inv = bc[1];
    float4 gg = ((const float4*)gam)[t];
    float4 bb = ((const float4*)bet)[t];
    float4 o4;
    o4.x = (v.x-m)*inv*gg.x + bb.x;
    o4.y = (v.y-m)*inv*gg.y + bb.y;
    o4.z = (v.z-m)*inv*gg.z + bb.z;
    o4.w = (v.w-m)*inv*gg.w + bb.w;
    ((float4*)(out + (size_t)row*D_))[t] = o4;
}

// ---------------- generic fp32 GEMM: C = A[M,K] @ B[K,N] (+bias)(+gelu) ----
// BM=128, BN=64, BK=16, 256 threads, 8x4 microtile, double-buffered smem.
#define GBM 128
#define GBN 64
#define GBK 16

template<int EPI>   // 0: plain, 1: +bias, 2: +bias +gelu
__global__ void __launch_bounds__(256)
gemm_kernel(const float* __restrict__ A, const float* __restrict__ Bm,
            const float* __restrict__ bias, float* __restrict__ C,
            int M, int N, int K)
{
    __shared__ float As[2][GBK][GBM];
    __shared__ float Bs[2][GBK][GBN];
    const int tid = threadIdx.x;
    const int tx = tid & 15, ty = tid >> 4;
    const int bm = blockIdx.y * GBM, bn = blockIdx.x * GBN;

    const int f0 = tid*2, f1 = tid*2+1;
    const int ar0 = f0 >> 2, acg0 = f0 & 3;
    const int ar1 = f1 >> 2, acg1 = f1 & 3;
    const int bk = tid >> 4, bcg = tid & 15;

    float acc[8][4] = {};
    const int nkt = K/GBK;

    // prologue: load tile 0 into buffer 0
    {
        float4 va0 = *(const float4*)(A + (size_t)(bm+ar0)*K + acg0*4);
        float4 va1 = *(const float4*)(A + (size_t)(bm+ar1)*K + acg1*4);
        float4 vb  = *(const float4*)(Bm + (size_t)bk*N + bn + bcg*4);
        As[0][acg0*4+0][ar0]=va0.x; As[0][acg0*4+1][ar0]=va0.y;
        As[0][acg0*4+2][ar0]=va0.z; As[0][acg0*4+3][ar0]=va0.w;
        As[0][acg1*4+0][ar1]=va1.x; As[0][acg1*4+1][ar1]=va1.y;
        As[0][acg1*4+2][ar1]=va1.z; As[0][acg1*4+3][ar1]=va1.w;
        *(float4*)&Bs[0][bk][bcg*4] = vb;
    }
    __syncthreads();

    for (int kt=0; kt<nkt; kt++){
        const int cb = kt & 1, nb = cb ^ 1;
        float4 va0, va1, vb;
        const bool more = (kt+1 < nkt);
        if (more){
            const float* ap = A + (size_t)(kt+1)*GBK;
            va0 = *(const float4*)(ap + (size_t)(bm+ar0)*K + acg0*4);
            va1 = *(const float4*)(ap + (size_t)(bm+ar1)*K + acg1*4);
            vb  = *(const float4*)(Bm + (size_t)((kt+1)*GBK + bk)*N + bn + bcg*4);
        }
        #pragma unroll
        for (int kk=0; kk<GBK; kk++){
            float a[8], b[4];
            #pragma unroll
            for (int i=0;i<8;i++) a[i] = As[cb][kk][ty*8+i];
            #pragma unroll
            for (int j=0;j<4;j++) b[j] = Bs[cb][kk][tx*4+j];
            #pragma unroll
            for (int i=0;i<8;i++)
                #pragma unroll
                for (int j=0;j<4;j++)
                    acc[i][j] = fmaf(a[i], b[j], acc[i][j]);
        }
        if (more){
            As[nb][acg0*4+0][ar0]=va0.x; As[nb][acg0*4+1][ar0]=va0.y;
            As[nb][acg0*4+2][ar0]=va0.z; As[nb][acg0*4+3][ar0]=va0.w;
            As[nb][acg1*4+0][ar1]=va1.x; As[nb][acg1*4+1][ar1]=va1.y;
            As[nb][acg1*4+2][ar1]=va1.z; As[nb][acg1*4+3][ar1]=va1.w;
            *(float4*)&Bs[nb][bk][bcg*4] = vb;
        }
        __syncthreads();
    }

    // epilogue
    float4 bv = make_float4(0.f,0.f,0.f,0.f);
    if (EPI >= 1) bv = *(const float4*)(bias + bn + tx*4);
    #pragma unroll
    for (int i=0;i<8;i++){
        float4 o4;
        o4.x = acc[i][0]; o4.y = acc[i][1]; o4.z = acc[i][2]; o4.w = acc[i][3];
        if (EPI >= 1){ o4.x+=bv.x; o4.y+=bv.y; o4.z+=bv.z; o4.w+=bv.w; }
        if (EPI == 2){ o4.x=gelu_t(o4.x); o4.y=gelu_t(o4.y); o4.z=gelu_t(o4.z); o4.w=gelu_t(o4.w); }
        *(float4*)(C + (size_t)(bm + ty*8 + i)*N + bn + tx*4) = o4;
    }
}

// ---------------- fused attention scores: AC + shifted BD + causal mask ----
// scores[b,h,q,k] = scale*((q+u)·k[k] + (q+v)·r[S-1-(q-k)])  for k<=q, else -1e30
__global__ void __launch_bounds__(256)
score_kernel(const float* __restrict__ up, const float* __restrict__ vp){
    if (blockIdx.x > blockIdx.y) return;           // upper-triangular tiles skipped
    const int kt0 = blockIdx.x*64, qt0 = blockIdx.y*64;
    const int bh = blockIdx.z, b = bh >> 4, h = bh & 15;
    __shared__ float qs[16][64];
    __shared__ float ks[16][64];
    __shared__ float rs[16][128];
    __shared__ float wv[16];
    const int tid = threadIdx.x;
    const int tx = tid & 15, ty = tid >> 4;
    const int qi = tid & 63, dg = tid >> 6;
    const int jj = tid & 127, dg2 = tid >> 7;
    const int rbase = S_ - 64 - qt0 + kt0;
    float accA[4][4] = {}, accB[4][4] = {};

    for (int dc=0; dc<4; dc++){
        const int d0 = dc*16;
        {
            float4 vq = *(const float4*)(g_q + ((size_t)(b*S_ + qt0 + qi))*D_ + h*DH_ + d0 + dg*4);
            float4 vu = *(const float4*)(up + h*DH_ + d0 + dg*4);
            qs[dg*4+0][qi]=vq.x+vu.x; qs[dg*4+1][qi]=vq.y+vu.y;
            qs[dg*4+2][qi]=vq.z+vu.z; qs[dg*4+3][qi]=vq.w+vu.w;
            float4 vk = *(const float4*)(g_k + ((size_t)(b*S_ + kt0 + qi))*D_ + h*DH_ + d0 + dg*4);
            ks[dg*4+0][qi]=vk.x; ks[dg*4+1][qi]=vk.y;
            ks[dg*4+2][qi]=vk.z; ks[dg*4+3][qi]=vk.w;
        }
        {
            int rrow = rbase + jj;
            if (rrow >= 0 && rrow < S_){
                const float* pr = g_r + (size_t)rrow*D_ + h*DH_ + d0 + dg2*8;
                float4 v0 = *(const float4*)pr;
                float4 v1 = *(const float4*)(pr+4);
                rs[dg2*8+0][jj]=v0.x; rs[dg2*8+1][jj]=v0.y; rs[dg2*8+2][jj]=v0.z; rs[dg2*8+3][jj]=v0.w;
                rs[dg2*8+4][jj]=v1.x; rs[dg2*8+5][jj]=v1.y; rs[dg2*8+6][jj]=v1.z; rs[dg2*8+7][jj]=v1.w;
            } else {
                #pragma unroll
                for (int c=0;c<8;c++) rs[dg2*8+c][jj]=0.f;
            }
        }
        if (tid < 16) wv[tid] = vp[h*DH_ + d0 + tid] - up[h*DH_ + d0 + tid];
        __syncthreads();
        #pragma unroll
        for (int dd=0; dd<16; dd++){
            float a[4], kv[4];
            #pragma unroll
            for (int i=0;i<4;i++) a[i]  = qs[dd][ty*4+i];
            #pragma unroll
            for (int j=0;j<4;j++) kv[j] = ks[dd][tx*4+j];
            float w = wv[dd];
            #pragma unroll
            for (int i=0;i<4;i++){
                float av = a[i] + w;   // (q+u) + (v-u) = q+v
                #pragma unroll
                for (int j=0;j<4;j++){
                    accA[i][j] = fmaf(a[i], kv[j], accA[i][j]);
                    accB[i][j] = fmaf(av, rs[dd][63 + tx*4 + j - ty*4 - i], accB[i][j]);
                }
            }
        }
        __syncthreads();
    }
    #pragma unroll
    for (int i=0;i<4;i++){
        int q = qt0 + ty*4 + i;
        #pragma unroll
        for (int j=0;j<4;j++){
            int k = kt0 + tx*4 + j;
            float sc = (k <= q) ? (accA[i][j] + accB[i][j]) * 0.125f : -1e30f;
            g_aw[((size_t)bh*S_ + q)*S_ + k] = sc;
        }
    }
}

// ---------------- softmax per row (masked-aware, pad-query -> 0) -----------
__global__ void softmax_kernel(const int* __restrict__ text){
    const int q = blockIdx.x, bh = blockIdx.y, b = bh >> 4;
    float* row = g_aw + ((size_t)bh*S_ + q)*S_;
    const int t = threadIdx.x;
    float4 v = ((float4*)row)[t];
    const int k0 = t*4;
    float vals[4] = {v.x, v.y, v.z, v.w};
    float mx = -1e30f;
    #pragma unroll
    for (int c=0;c<4;c++) if (k0+c <= q) mx = fmaxf(mx, vals[c]);
    #pragma unroll
    for (int o=16;o;o>>=1) mx = fmaxf(mx, __shfl_xor_sync(0xffffffffu, mx, o));
    __shared__ float sh[8], bc[2];
    int w = t>>5, lane = t&31;
    if (!lane) sh[w] = mx;
    __syncthreads();
    if (t==0){ float m=sh[0]; for (int i=1;i<8;i++) m=fmaxf(m,sh[i]); bc[0]=m; }
    __syncthreads();
    mx = bc[0];
    float e[4]; float s = 0.f;
    #pragma unroll
    for (int c=0;c<4;c++){ e[c] = (k0+c <= q) ? __expf(vals[c]-mx) : 0.f; s += e[c]; }
    #pragma unroll
    for (int o=16;o;o>>=1) s += __shfl_xor_sync(0xffffffffu, s, o);
    if (!lane) sh[w] = s;
    __syncthreads();
    if (t==0){ float m=0.f; for (int i=0;i<8;i++) m+=sh[i]; bc[1]=m; }
    __syncthreads();
    bool padq = (text[b*CTX_ + q] == PAD_);
    float inv = padq ? 0.f : 1.0f/bc[1];
    v.x=e[0]*inv; v.y=e[1]*inv; v.z=e[2]*inv; v.w=e[3]*inv;
    ((float4*)row)[t] = v;
}

// ---------------- o = aw @ v (batched per (b,h)) ----------------------------
__global__ void __launch_bounds__(256)
av_kernel(){
    const int q0 = blockIdx.x*64;
    const int bh = blockIdx.y, b = bh>>4, h = bh&15;
    __shared__ float As[16][64];
    __shared__ float Bs[16][64];
    const int tid = threadIdx.x;
    const int tx = tid&15, ty = tid>>4;
    const int aqi = tid>>2, akg = tid&3;
    const int bkk = tid>>4, bdg = tid&15;
    float acc[4][4] = {};
    for (int kt=0; kt<64; kt++){
        float4 va = *(const float4*)(g_aw + ((size_t)bh*S_ + q0 + aqi)*S_ + kt*16 + akg*4);
        As[akg*4+0][aqi]=va.x; As[akg*4+1][aqi]=va.y; As[akg*4+2][aqi]=va.z; As[akg*4+3][aqi]=va.w;
        float4 vb = *(const float4*)(g_v + ((size_t)(b*S_ + kt*16 + bkk))*D_ + h*DH_ + bdg*4);
        *(float4*)&Bs[bkk][bdg*4] = vb;
        __syncthreads();
        #pragma unroll
        for (int kk=0;kk<16;kk++){
            float a[4], bb[4];
            #pragma unroll
            for (int i=0;i<4;i++) a[i]=As[kk][ty*4+i];
            #pragma unroll
            for (int j=0;j<4;j++) bb[j]=Bs[kk][tx*4+j];
            #pragma unroll
            for (int i=0;i<4;i++)
                #pragma unroll
                for (int j=0;j<4;j++)
                    acc[i][j] = fmaf(a[i], bb[j], acc[i][j]);
        }
        __syncthreads();
    }
    #pragma unroll
    for (int i=0;i<4;i++){
        float4 o4; o4.x=acc[i][0]; o4.y=acc[i][1]; o4.z=acc[i][2]; o4.w=acc[i][3];
        *(float4*)(g_o + ((size_t)(b*S_ + q0 + ty*4 + i))*D_ + h*DH_ + tx*4) = o4;
    }
}

// ---------------- residual fusions -----------------------------------------
__global__ void resid_attn_kernel(const float* __restrict__ bfc){
    int idx = blockIdx.x*256 + threadIdx.x;       // over B*S*D/4
    int d4 = idx & (D_/4 - 1);
    float4 x  = ((float4*)g_x)[idx];
    float4 t  = ((const float4*)g_tmp)[idx];
    float4 xn = ((const float4*)g_xn)[idx];
    float4 bb = ((const float4*)bfc)[d4];
    x.x += t.x + xn.x + bb.x;
    x.y += t.y + xn.y + bb.y;
    x.z += t.z + xn.z + bb.z;
    x.w += t.w + xn.w + bb.w;
    ((float4*)g_x)[idx] = x;
}

__global__ void resid_add_kernel(){
    int idx = blockIdx.x*256 + threadIdx.x;
    float4 x = ((float4*)g_x)[idx];
    float4 t = ((const float4*)g_tmp)[idx];
    x.x+=t.x; x.y+=t.y; x.z+=t.z; x.w+=t.w;
    ((float4*)g_x)[idx] = x;
}

// ---------------- orchestration ---------------------------------------------
extern "C" void kernel_launch(void* const* d_in, const int* in_sizes, int n_in,
                              void* d_out, int out_size)
{
    (void)in_sizes; (void)n_in; (void)out_size;
    const int*   text = (const int*)  d_in[0];
    const float* emb  = (const float*)d_in[1];
    const float* u    = (const float*)d_in[2];
    const float* vbp  = (const float*)d_in[3];
    const float* Wq   = (const float*)d_in[4];
    const float* Wk   = (const float*)d_in[5];
    const float* Wv   = (const float*)d_in[6];
    const float* Wr   = (const float*)d_in[7];
    const float* Wfc  = (const float*)d_in[8];
    const float* bfc  = (const float*)d_in[9];
    const float* ln1g = (const float*)d_in[10];
    const float* ln1b = (const float*)d_in[11];
    const float* ln2g = (const float*)d_in[12];
    const float* ln2b = (const float*)d_in[13];
    const float* W1   = (const float*)d_in[14];
    const float* b1   = (const float*)d_in[15];
    const float* W2   = (const float*)d_in[16];
    const float* b2   = (const float*)d_in[17];
    const float* lnfg = (const float*)d_in[18];
    const float* lnfb = (const float*)d_in[19];
    const float* Wlm  = (const float*)d_in[20];
    const float* blm  = (const float*)d_in[21];
    float* out = (float*)d_out;

    float *px,*pxn,*pq,*pk,*pv,*po,*ptmp,*prel,*pr,*pff;
    cudaGetSymbolAddress((void**)&px,   g_x);
    cudaGetSymbolAddress((void**)&pxn,  g_xn);
    cudaGetSymbolAddress((void**)&pq,   g_q);
    cudaGetSymbolAddress((void**)&pk,   g_k);
    cudaGetSymbolAddress((void**)&pv,   g_v);
    cudaGetSymbolAddress((void**)&po,   g_o);
    cudaGetSymbolAddress((void**)&ptmp, g_tmp);
    cudaGetSymbolAddress((void**)&prel, g_rel);
    cudaGetSymbolAddress((void**)&pr,   g_r);
    cudaGetSymbolAddress((void**)&pff,  g_ff);

    const int MR = B_*S_;                     // 2048 rows

    embed_kernel<<<2048,256>>>(text, emb);
    rel_kernel  <<<2048,256>>>();

    for (int l=0; l<L_; l++){
        ln_kernel<<<MR,256>>>(px, pxn, ln1g + l*D_, ln1b + l*D_);

        gemm_kernel<0><<<dim3(D_/GBN, MR/GBM),256>>>(pxn, Wq + (size_t)l*D_*D_, nullptr, pq, MR, D_, D_);
        gemm_kernel<0><<<dim3(D_/GBN, MR/GBM),256>>>(pxn, Wk + (size_t)l*D_*D_, nullptr, pk, MR, D_, D_);
        gemm_kernel<0><<<dim3(D_/GBN, MR/GBM),256>>>(pxn, Wv + (size_t)l*D_*D_, nullptr, pv, MR, D_, D_);
        gemm_kernel<0><<<dim3(D_/GBN, S_/GBM),256>>>(prel, Wr + (size_t)l*D_*D_, nullptr, pr, S_, D_, D_);

        score_kernel  <<<dim3(16,16,B_*H_),256>>>(u, vbp);
        softmax_kernel<<<dim3(S_, B_*H_),256>>>(text);
        av_kernel     <<<dim3(16, B_*H_),256>>>();

        gemm_kernel<0><<<dim3(D_/GBN, MR/GBM),256>>>(po, Wfc + (size_t)l*D_*D_, nullptr, ptmp, MR, D_, D_);
        resid_attn_kernel<<<2048,256>>>(bfc + l*D_);

        ln_kernel<<<MR,256>>>(px, pxn, ln2g + l*D_, ln2b + l*D_);
        gemm_kernel<2><<<dim3(FF_/GBN, MR/GBM),256>>>(pxn, W1 + (size_t)l*D_*FF_, b1 + l*FF_, pff, MR, FF_, D_);
        gemm_kernel<2><<<dim3(D_/GBN, MR/GBM),256>>>(pff, W2 + (size_t)l*FF_*D_, b2 + l*D_, ptmp, MR, D_, FF_);
        resid_add_kernel<<<2048,256>>>();
    }

    ln_kernel<<<MR,256>>>(px, pxn, lnfg, lnfb);
    gemm_kernel<1><<<dim3(V_/GBN, MR/GBM),256>>>(pxn, Wlm, blm, out, MR, V_, D_);
}

// round 2
// speedup vs baseline: 2.0101x; 2.0101x over previous
#include <cuda_runtime.h>
#include <stdint.h>
#include <math.h>

#define B_   2
#define S_   1024
#define D_   1024
#define H_   16
#define DH_  64
#define FF_  4096
#define V_   32000
#define L_   4
#define PAD_ 3
#define CTX_ 1025

// ---------------- scratch (static device globals; no runtime alloc) -------
__device__ float g_x  [B_*S_*D_];
__device__ float g_xn [B_*S_*D_];
__device__ float g_q  [B_*S_*D_];
__device__ float g_k  [B_*S_*D_];
__device__ float g_v  [B_*S_*D_];
__device__ float g_o  [B_*S_*D_];
__device__ float g_tmp[B_*S_*D_];
__device__ float g_rel[S_*D_];
__device__ float g_r  [S_*D_];
__device__ float g_ff [B_*S_*FF_];
__device__ float g_aw [(size_t)B_*H_*S_*S_];   // scores then attn weights (128 MB)

// ---------------- helpers --------------------------------------------------
__device__ __forceinline__ float gelu_t(float x){
    return 0.5f*x*(1.0f + tanhf(0.7978845608028654f*(x + 0.044715f*x*x*x)));
}
__device__ __forceinline__ uint32_t f2tf(float x){
    uint32_t y; asm("cvt.rna.tf32.f32 %0, %1;" : "=r"(y) : "f"(x)); return y;
}
__device__ __forceinline__ void mma_tf32(float c[4], const uint32_t a[4], const uint32_t b[2]){
    asm volatile(
      "mma.sync.aligned.m16n8k8.row.col.f32.tf32.tf32.f32 "
      "{%0,%1,%2,%3}, {%4,%5,%6,%7}, {%8,%9}, {%0,%1,%2,%3};\n"
      : "+f"(c[0]), "+f"(c[1]), "+f"(c[2]), "+f"(c[3])
      : "r"(a[0]), "r"(a[1]), "r"(a[2]), "r"(a[3]), "r"(b[0]), "r"(b[1]));
}

// ---------------- embedding ------------------------------------------------
__global__ void embed_kernel(const int* __restrict__ text, const float* __restrict__ emb){
    int idx = blockIdx.x*256 + threadIdx.x;        // over B*S*D/4
    int d4  = idx & (D_/4 - 1);
    int bs  = idx >> 8;
    int s   = bs & (S_-1);
    int b   = bs >> 10;
    int tok = text[b*CTX_ + s];
    ((float4*)g_x)[idx] = ((const float4*)(emb + (size_t)tok*D_))[d4];
}

// ---------------- sinusoidal relative positions ----------------------------
__global__ void rel_kernel(){
    int idx = blockIdx.x*256 + threadIdx.x;        // over S*(D/2)
    int j = idx & 511;
    int s = idx >> 9;
    float pos  = (float)(S_-1-s);
    float invf = powf(10000.0f, -(float)(2*j)/(float)D_);
    float a = pos*invf;
    g_rel[s*D_ + j]       = sinf(a);
    g_rel[s*D_ + j + 512] = cosf(a);
}

// ---------------- layernorm (one block per row, 256 thr, D=1024) -----------
__global__ void ln_kernel(const float* __restrict__ in, float* __restrict__ out,
                          const float* __restrict__ gam, const float* __restrict__ bet){
    int row = blockIdx.x;
    int t = threadIdx.x;
    const float4* x4 = (const float4*)(in + (size_t)row*D_);
    float4 v = x4[t];
    float s  = v.x+v.y+v.z+v.w;
    float s2 = v.x*v.x+v.y*v.y+v.z*v.z+v.w*v.w;
    #pragma unroll
    for (int o=16;o;o>>=1){ s += __shfl_xor_sync(0xffffffffu,s,o); s2 += __shfl_xor_sync(0xffffffffu,s2,o); }
    __shared__ float shs[8], shs2[8], bc[2];
    int w = t>>5, lane = t&31;
    if (!lane){ shs[w]=s; shs2[w]=s2; }
    __syncthreads();
    if (t==0){
        float ts=0.f, ts2=0.f;
        #pragma unroll
        for (int i=0;i<8;i++){ ts+=shs[i]; ts2+=shs2[i]; }
        float m   = ts*(1.0f/(float)D_);
        float var = ts2*(1.0f/(float)D_) - m*m;
        bc[0]=m; bc[1]=rsqrtf(var + 1e-5f);
    }
    __syncthreads();
    float m = bc[0], inv = bc[1];
    float4 gg = ((const float4*)gam)[t];
    float4 bb = ((const float4*)bet)[t];
    float4 o4;
    o4.x = (v.x-m)*inv*gg.x + bb.x;
    o4.y = (v.y-m)*inv*gg.y + bb.y;
    o4.z = (v.z-m)*inv*gg.z + bb.z;
    o4.w = (v.w-m)*inv*gg.w + bb.w;
    ((float4*)(out + (size_t)row*D_))[t] = o4;
}

// ================= tf32 tensor-core GEMM ====================================
// C[M,N] = A[M,K] @ B[K,N] (+bias)(+gelu). CTA tile 128x128x16, 256 threads.
// 8 warps in 4(m) x 2(n) grid; warp tile 32x64; mma.m16n8k8 tf32.
#define TBM 128
#define TBN 128
#define TBK 16
#define ASTRIDE 20     // As row stride in words (conflict-free fragment loads)
#define BSTRIDE 136    // Bs row stride in words

template<int EPI>   // 0: plain, 1: +bias, 2: +bias+gelu
__device__ __forceinline__ void tgemm_body(
    const float* __restrict__ A, const float* __restrict__ Bm,
    const float* __restrict__ bias, float* __restrict__ C,
    int N, int K)
{
    __shared__ uint32_t As[2][TBM][ASTRIDE];
    __shared__ uint32_t Bs[2][TBK][BSTRIDE];

    const int tid  = threadIdx.x;
    const int lane = tid & 31, wid = tid >> 5;
    const int wm = wid >> 1, wn = wid & 1;
    const int m0w = wm*32, n0w = wn*64;
    const int r = lane >> 2, cg = lane & 3;

    const int bm = blockIdx.y*TBM, bn = blockIdx.x*TBN;

    // fill mappings
    const int aRow0 = tid >> 2,           aCg = tid & 3;     // + i*64 rows
    const int bRow0 = tid >> 5,           bCg = tid & 31;    // + i*8 rows

    float acc[2][8][4];
    #pragma unroll
    for (int mt=0;mt<2;mt++)
        #pragma unroll
        for (int nt=0;nt<8;nt++)
            #pragma unroll
            for (int i=0;i<4;i++) acc[mt][nt][i]=0.f;

    const int nkt = K/TBK;

    // -------- prologue: fill buffer 0
    {
        #pragma unroll
        for (int i=0;i<2;i++){
            int row = aRow0 + i*64;
            float4 v = *(const float4*)(A + (size_t)(bm+row)*K + aCg*4);
            uint4 t; t.x=f2tf(v.x); t.y=f2tf(v.y); t.z=f2tf(v.z); t.w=f2tf(v.w);
            *(uint4*)&As[0][row][aCg*4] = t;
        }
        #pragma unroll
        for (int i=0;i<2;i++){
            int row = bRow0 + i*8;
            float4 v = *(const float4*)(Bm + (size_t)row*N + bn + bCg*4);
            uint4 t; t.x=f2tf(v.x); t.y=f2tf(v.y); t.z=f2tf(v.z); t.w=f2tf(v.w);
            *(uint4*)&Bs[0][row][bCg*4] = t;
        }
    }
    __syncthreads();

    for (int kt=0; kt<nkt; kt++){
        const int cb = kt & 1, nb = cb ^ 1;
        const bool more = (kt+1 < nkt);
        float4 pa[2], pb[2];
        if (more){
            const int k0 = (kt+1)*TBK;
            #pragma unroll
            for (int i=0;i<2;i++){
                int row = aRow0 + i*64;
                pa[i] = *(const float4*)(A + (size_t)(bm+row)*K + k0 + aCg*4);
            }
            #pragma unroll
            for (int i=0;i<2;i++){
                int row = bRow0 + i*8;
                pb[i] = *(const float4*)(Bm + (size_t)(k0+row)*N + bn + bCg*4);
            }
        }

        #pragma unroll
        for (int ks=0; ks<2; ks++){
            uint32_t af[2][4];
            #pragma unroll
            for (int mt=0;mt<2;mt++){
                int mb = m0w + mt*16 + r;
                af[mt][0] = As[cb][mb   ][ks*8 + cg    ];
                af[mt][1] = As[cb][mb+8 ][ks*8 + cg    ];
                af[mt][2] = As[cb][mb   ][ks*8 + cg + 4];
                af[mt][3] = As[cb][mb+8 ][ks*8 + cg + 4];
            }
            uint32_t bf[8][2];
            #pragma unroll
            for (int nt=0;nt<8;nt++){
                bf[nt][0] = Bs[cb][ks*8 + cg    ][n0w + nt*8 + r];
                bf[nt][1] = Bs[cb][ks*8 + cg + 4][n0w + nt*8 + r];
            }
            #pragma unroll
            for (int mt=0;mt<2;mt++)
                #pragma unroll
                for (int nt=0;nt<8;nt++)
                    mma_tf32(acc[mt][nt], af[mt], bf[nt]);
        }

        if (more){
            #pragma unroll
            for (int i=0;i<2;i++){
                int row = aRow0 + i*64;
                uint4 t; t.x=f2tf(pa[i].x); t.y=f2tf(pa[i].y); t.z=f2tf(pa[i].z); t.w=f2tf(pa[i].w);
                *(uint4*)&As[nb][row][aCg*4] = t;
            }
            #pragma unroll
            for (int i=0;i<2;i++){
                int row = bRow0 + i*8;
                uint4 t; t.x=f2tf(pb[i].x); t.y=f2tf(pb[i].y); t.z=f2tf(pb[i].z); t.w=f2tf(pb[i].w);
                *(uint4*)&Bs[nb][row][bCg*4] = t;
            }
        }
        __syncthreads();
    }

    // -------- epilogue
    #pragma unroll
    for (int mt=0;mt<2;mt++){
        int row0 = bm + m0w + mt*16 + r;
        #pragma unroll
        for (int nt=0;nt<8;nt++){
            int col = bn + n0w + nt*8 + cg*2;
            float2 b2 = make_float2(0.f,0.f);
            if (EPI >= 1) b2 = *(const float2*)(bias + col);
            float2 v0, v1;
            v0.x = acc[mt][nt][0] + b2.x; v0.y = acc[mt][nt][1] + b2.y;
            v1.x = acc[mt][nt][2] + b2.x; v1.y = acc[mt][nt][3] + b2.y;
            if (EPI == 2){
                v0.x = gelu_t(v0.x); v0.y = gelu_t(v0.y);
                v1.x = gelu_t(v1.x); v1.y = gelu_t(v1.y);
            }
            *(float2*)(C + (size_t)row0*N + col)     = v0;
            *(float2*)(C + (size_t)(row0+8)*N + col) = v1;
        }
    }
}

template<int EPI>
__global__ void __launch_bounds__(256)
tgemm_kernel(const float* __restrict__ A, const float* __restrict__ Bm,
             const float* __restrict__ bias, float* __restrict__ C, int N, int K)
{
    tgemm_body<EPI>(A, Bm, bias, C, N, K);
}

// QKV + R fused launch: z selects which GEMM.
__global__ void __launch_bounds__(256)
qkvr_kernel(const float* __restrict__ xn, const float* __restrict__ rel,
            const float* __restrict__ Wq, const float* __restrict__ Wk,
            const float* __restrict__ Wv, const float* __restrict__ Wr,
            float* __restrict__ q, float* __restrict__ k,
            float* __restrict__ v, float* __restrict__ rr)
{
    const int z = blockIdx.z;
    if (z == 3 && blockIdx.y*TBM >= S_) return;   // R gemm has M=1024
    const float* A = (z < 3) ? xn : rel;
    const float* W = (z==0) ? Wq : (z==1) ? Wk : (z==2) ? Wv : Wr;
    float*       C = (z==0) ? q  : (z==1) ? k  : (z==2) ? v  : rr;
    tgemm_body<0>(A, W, nullptr, C, D_, D_);
}

// ---------------- fused attention scores: AC + shifted BD + causal mask ----
__global__ void __launch_bounds__(256)
score_kernel(const float* __restrict__ up, const float* __restrict__ vp){
    if (blockIdx.x > blockIdx.y) return;
    const int kt0 = blockIdx.x*64, qt0 = blockIdx.y*64;
    const int bh = blockIdx.z, b = bh >> 4, h = bh & 15;
    __shared__ float qs[16][64];
    __shared__ float ks[16][64];
    __shared__ float rs[16][128];
    __shared__ float wv[16];
    const int tid = threadIdx.x;
    const int tx = tid & 15, ty = tid >> 4;
    const int qi = tid & 63, dg = tid >> 6;
    const int jj = tid & 127, dg2 = tid >> 7;
    const int rbase = S_ - 64 - qt0 + kt0;
    float accA[4][4] = {}, accB[4][4] = {};

    for (int dc=0; dc<4; dc++){
        const int d0 = dc*16;
        {
            float4 vq = *(const float4*)(g_q + ((size_t)(b*S_ + qt0 + qi))*D_ + h*DH_ + d0 + dg*4);
            float4 vu = *(const float4*)(up + h*DH_ + d0 + dg*4);
            qs[dg*4+0][qi]=vq.x+vu.x; qs[dg*4+1][qi]=vq.y+vu.y;
            qs[dg*4+2][qi]=vq.z+vu.z; qs[dg*4+3][qi]=vq.w+vu.w;
            float4 vk = *(const float4*)(g_k + ((size_t)(b*S_ + kt0 + qi))*D_ + h*DH_ + d0 + dg*4);
            ks[dg*4+0][qi]=vk.x; ks[dg*4+1][qi]=vk.y;
            ks[dg*4+2][qi]=vk.z; ks[dg*4+3][qi]=vk.w;
        }
        {
            int rrow = rbase + jj;
            if (rrow >= 0 && rrow < S_){
                const float* pr = g_r + (size_t)rrow*D_ + h*DH_ + d0 + dg2*8;
                float4 v0 = *(const float4*)pr;
                float4 v1 = *(const float4*)(pr+4);
                rs[dg2*8+0][jj]=v0.x; rs[dg2*8+1][jj]=v0.y; rs[dg2*8+2][jj]=v0.z; rs[dg2*8+3][jj]=v0.w;
                rs[dg2*8+4][jj]=v1.x; rs[dg2*8+5][jj]=v1.y; rs[dg2*8+6][jj]=v1.z; rs[dg2*8+7][jj]=v1.w;
            } else {
                #pragma unroll
                for (int c=0;c<8;c++) rs[dg2*8+c][jj]=0.f;
            }
        }
        if (tid < 16) wv[tid] = vp[h*DH_ + d0 + tid] - up[h*DH_ + d0 + tid];
        __syncthreads();
        #pragma unroll
        for (int dd=0; dd<16; dd++){
            float a[4], kv[4];
            #pragma unroll
            for (int i=0;i<4;i++) a[i]  = qs[dd][ty*4+i];
            #pragma unroll
            for (int j=0;j<4;j++) kv[j] = ks[dd][tx*4+j];
            float w = wv[dd];
            #pragma unroll
            for (int i=0;i<4;i++){
                float av = a[i] + w;
                #pragma unroll
                for (int j=0;j<4;j++){
                    accA[i][j] = fmaf(a[i], kv[j], accA[i][j]);
                    accB[i][j] = fmaf(av, rs[dd][63 + tx*4 + j - ty*4 - i], accB[i][j]);
                }
            }
        }
        __syncthreads();
    }
    #pragma unroll
    for (int i=0;i<4;i++){
        int q = qt0 + ty*4 + i;
        #pragma unroll
        for (int j=0;j<4;j++){
            int k = kt0 + tx*4 + j;
            float sc = (k <= q) ? (accA[i][j] + accB[i][j]) * 0.125f : -1e30f;
            g_aw[((size_t)bh*S_ + q)*S_ + k] = sc;
        }
    }
}

// ---------------- softmax per row -------------------------------------------
__global__ void softmax_kernel(const int* __restrict__ text){
    const int q = blockIdx.x, bh = blockIdx.y, b = bh >> 4;
    float* row = g_aw + ((size_t)bh*S_ + q)*S_;
    const int t = threadIdx.x;
    float4 v = ((float4*)row)[t];
    const int k0 = t*4;
    float vals[4] = {v.x, v.y, v.z, v.w};
    float mx = -1e30f;
    #pragma unroll
    for (int c=0;c<4;c++) if (k0+c <= q) mx = fmaxf(mx, vals[c]);
    #pragma unroll
    for (int o=16;o;o>>=1) mx = fmaxf(mx, __shfl_xor_sync(0xffffffffu, mx, o));
    __shared__ float sh[8], bc[2];
    int w = t>>5, lane = t&31;
    if (!lane) sh[w] = mx;
    __syncthreads();
    if (t==0){ float m=sh[0]; for (int i=1;i<8;i++) m=fmaxf(m,sh[i]); bc[0]=m; }
    __syncthreads();
    mx = bc[0];
    float e[4]; float s = 0.f;
    #pragma unroll
    for (int c=0;c<4;c++){ e[c] = (k0+c <= q) ? __expf(vals[c]-mx) : 0.f; s += e[c]; }
    #pragma unroll
    for (int o=16;o;o>>=1) s += __shfl_xor_sync(0xffffffffu, s, o);
    if (!lane) sh[w] = s;
    __syncthreads();
    if (t==0){ float m=0.f; for (int i=0;i<8;i++) m+=sh[i]; bc[1]=m; }
    __syncthreads();
    bool padq = (text[b*CTX_ + q] == PAD_);
    float inv = padq ? 0.f : 1.0f/bc[1];
    v.x=e[0]*inv; v.y=e[1]*inv; v.z=e[2]*inv; v.w=e[3]*inv;
    ((float4*)row)[t] = v;
}

// ---------------- o = aw @ v (batched per (b,h)) ----------------------------
__global__ void __launch_bounds__(256)
av_kernel(){
    const int q0 = blockIdx.x*64;
    const int bh = blockIdx.y, b = bh>>4, h = bh&15;
    __shared__ float As2[16][64];
    __shared__ float Bs2[16][64];
    const int tid = threadIdx.x;
    const int tx = tid&15, ty = tid>>4;
    const int aqi = tid>>2, akg = tid&3;
    const int bkk = tid>>4, bdg = tid&15;
    float acc[4][4] = {};
    for (int kt=0; kt<64; kt++){
        float4 va = *(const float4*)(g_aw + ((size_t)bh*S_ + q0 + aqi)*S_ + kt*16 + akg*4);
        As2[akg*4+0][aqi]=va.x; As2[akg*4+1][aqi]=va.y; As2[akg*4+2][aqi]=va.z; As2[akg*4+3][aqi]=va.w;
        float4 vb = *(const float4*)(g_v + ((size_t)(b*S_ + kt*16 + bkk))*D_ + h*DH_ + bdg*4);
        *(float4*)&Bs2[bkk][bdg*4] = vb;
        __syncthreads();
        #pragma unroll
        for (int kk=0;kk<16;kk++){
            float a[4], bb[4];
            #pragma unroll
            for (int i=0;i<4;i++) a[i]=As2[kk][ty*4+i];
            #pragma unroll
            for (int j=0;j<4;j++) bb[j]=Bs2[kk][tx*4+j];
            #pragma unroll
            for (int i=0;i<4;i++)
                #pragma unroll
                for (int j=0;j<4;j++)
                    acc[i][j] = fmaf(a[i], bb[j], acc[i][j]);
        }
        __syncthreads();
    }
    #pragma unroll
    for (int i=0;i<4;i++){
        float4 o4; o4.x=acc[i][0]; o4.y=acc[i][1]; o4.z=acc[i][2]; o4.w=acc[i][3];
        *(float4*)(g_o + ((size_t)(b*S_ + q0 + ty*4 + i))*D_ + h*DH_ + tx*4) = o4;
    }
}

// ---------------- residual fusions -----------------------------------------
__global__ void resid_attn_kernel(const float* __restrict__ bfc){
    int idx = blockIdx.x*256 + threadIdx.x;
    int d4 = idx & (D_/4 - 1);
    float4 x  = ((float4*)g_x)[idx];
    float4 t  = ((const float4*)g_tmp)[idx];
    float4 xn = ((const float4*)g_xn)[idx];
    float4 bb = ((const float4*)bfc)[d4];
    x.x += t.x + xn.x + bb.x;
    x.y += t.y + xn.y + bb.y;
    x.z += t.z + xn.z + bb.z;
    x.w += t.w + xn.w + bb.w;
    ((float4*)g_x)[idx] = x;
}

__global__ void resid_add_kernel(){
    int idx = blockIdx.x*256 + threadIdx.x;
    float4 x = ((float4*)g_x)[idx];
    float4 t = ((const float4*)g_tmp)[idx];
    x.x+=t.x; x.y+=t.y; x.z+=t.z; x.w+=t.w;
    ((float4*)g_x)[idx] = x;
}

// ---------------- orchestration ---------------------------------------------
extern "C" void kernel_launch(void* const* d_in, const int* in_sizes, int n_in,
                              void* d_out, int out_size)
{
    (void)in_sizes; (void)n_in; (void)out_size;
    const int*   text = (const int*)  d_in[0];
    const float* emb  = (const float*)d_in[1];
    const float* u    = (const float*)d_in[2];
    const float* vbp  = (const float*)d_in[3];
    const float* Wq   = (const float*)d_in[4];
    const float* Wk   = (const float*)d_in[5];
    const float* Wv   = (const float*)d_in[6];
    const float* Wr   = (const float*)d_in[7];
    const float* Wfc  = (const float*)d_in[8];
    const float* bfc  = (const float*)d_in[9];
    const float* ln1g = (const float*)d_in[10];
    const float* ln1b = (const float*)d_in[11];
    const float* ln2g = (const float*)d_in[12];
    const float* ln2b = (const float*)d_in[13];
    const float* W1   = (const float*)d_in[14];
    const float* b1   = (const float*)d_in[15];
    const float* W2   = (const float*)d_in[16];
    const float* b2   = (const float*)d_in[17];
    const float* lnfg = (const float*)d_in[18];
    const float* lnfb = (const float*)d_in[19];
    const float* Wlm  = (const float*)d_in[20];
    const float* blm  = (const float*)d_in[21];
    float* out = (float*)d_out;

    float *px,*pxn,*pq,*pk,*pv,*po,*ptmp,*prel,*pr,*pff;
    cudaGetSymbolAddress((void**)&px,   g_x);
    cudaGetSymbolAddress((void**)&pxn,  g_xn);
    cudaGetSymbolAddress((void**)&pq,   g_q);
    cudaGetSymbolAddress((void**)&pk,   g_k);
    cudaGetSymbolAddress((void**)&pv,   g_v);
    cudaGetSymbolAddress((void**)&po,   g_o);
    cudaGetSymbolAddress((void**)&ptmp, g_tmp);
    cudaGetSymbolAddress((void**)&prel, g_rel);
    cudaGetSymbolAddress((void**)&pr,   g_r);
    cudaGetSymbolAddress((void**)&pff,  g_ff);

    const int MR = B_*S_;                     // 2048 rows

    embed_kernel<<<2048,256>>>(text, emb);
    rel_kernel  <<<2048,256>>>();

    for (int l=0; l<L_; l++){
        ln_kernel<<<MR,256>>>(px, pxn, ln1g + l*D_, ln1b + l*D_);

        qkvr_kernel<<<dim3(D_/TBN, MR/TBM, 4),256>>>(
            pxn, prel,
            Wq + (size_t)l*D_*D_, Wk + (size_t)l*D_*D_,
            Wv + (size_t)l*D_*D_, Wr + (size_t)l*D_*D_,
            pq, pk, pv, pr);

        score_kernel  <<<dim3(16,16,B_*H_),256>>>(u, vbp);
        softmax_kernel<<<dim3(S_, B_*H_),256>>>(text);
        av_kernel     <<<dim3(16, B_*H_),256>>>();

        tgemm_kernel<0><<<dim3(D_/TBN, MR/TBM),256>>>(po, Wfc + (size_t)l*D_*D_, nullptr, ptmp, D_, D_);
        resid_attn_kernel<<<2048,256>>>(bfc + l*D_);

        ln_kernel<<<MR,256>>>(px, pxn, ln2g + l*D_, ln2b + l*D_);
        tgemm_kernel<2><<<dim3(FF_/TBN, MR/TBM),256>>>(pxn, W1 + (size_t)l*D_*FF_, b1 + l*FF_, pff, FF_, D_);
        tgemm_kernel<2><<<dim3(D_/TBN, MR/TBM),256>>>(pff, W2 + (size_t)l*FF_*D_, b2 + l*D_, ptmp, D_, FF_);
        resid_add_kernel<<<2048,256>>>();
    }

    ln_kernel<<<MR,256>>>(px, pxn, lnfg, lnfb);
    tgemm_kernel<1><<<dim3(V_/TBN, MR/TBM),256>>>(pxn, Wlm, blm, out, V_, D_);
}

// round 3
// speedup vs baseline: 2.3546x; 1.1714x over previous
#include <cuda_runtime.h>
#include <stdint.h>
#include <math.h>

#define B_   2
#define S_   1024
#define D_   1024
#define H_   16
#define DH_  64
#define FF_  4096
#define V_   32000
#define L_   4
#define PAD_ 3
#define CTX_ 1025

// ---------------- scratch (static device globals; no runtime alloc) -------
__device__ float g_x  [B_*S_*D_];
__device__ float g_xn [B_*S_*D_];
__device__ float g_q  [B_*S_*D_];
__device__ float g_k  [B_*S_*D_];
__device__ float g_v  [B_*S_*D_];
__device__ float g_o  [B_*S_*D_];
__device__ float g_tmp[B_*S_*D_];
__device__ float g_rel[S_*D_];
__device__ float g_r  [S_*D_];
__device__ float g_ff [B_*S_*FF_];
__device__ float g_aw [(size_t)B_*H_*S_*S_];   // scores then attn weights (128 MB)
__device__ float g_uk [B_*H_*S_];              // u·k[b,h,key]
__device__ float g_vr [H_*S_];                 // v·r[h,rrow]

// ---------------- helpers --------------------------------------------------
__device__ __forceinline__ float gelu_t(float x){
    return 0.5f*x*(1.0f + tanhf(0.7978845608028654f*(x + 0.044715f*x*x*x)));
}
__device__ __forceinline__ uint32_t f2tf(float x){
    uint32_t y; asm("cvt.rna.tf32.f32 %0, %1;" : "=r"(y) : "f"(x)); return y;
}
__device__ __forceinline__ void mma_tf32(float c[4], const uint32_t a[4], const uint32_t b[2]){
    asm volatile(
      "mma.sync.aligned.m16n8k8.row.col.f32.tf32.tf32.f32 "
      "{%0,%1,%2,%3}, {%4,%5,%6,%7}, {%8,%9}, {%0,%1,%2,%3};\n"
      : "+f"(c[0]), "+f"(c[1]), "+f"(c[2]), "+f"(c[3])
      : "r"(a[0]), "r"(a[1]), "r"(a[2]), "r"(a[3]), "r"(b[0]), "r"(b[1]));
}

// ---------------- embedding ------------------------------------------------
__global__ void embed_kernel(const int* __restrict__ text, const float* __restrict__ emb){
    int idx = blockIdx.x*256 + threadIdx.x;
    int d4  = idx & (D_/4 - 1);
    int bs  = idx >> 8;
    int s   = bs & (S_-1);
    int b   = bs >> 10;
    int tok = text[b*CTX_ + s];
    ((float4*)g_x)[idx] = ((const float4*)(emb + (size_t)tok*D_))[d4];
}

// ---------------- sinusoidal relative positions ----------------------------
__global__ void rel_kernel(){
    int idx = blockIdx.x*256 + threadIdx.x;
    int j = idx & 511;
    int s = idx >> 9;
    float pos  = (float)(S_-1-s);
    float invf = powf(10000.0f, -(float)(2*j)/(float)D_);
    float a = pos*invf;
    g_rel[s*D_ + j]       = sinf(a);
    g_rel[s*D_ + j + 512] = cosf(a);
}

// ---------------- layernorm ------------------------------------------------
__global__ void ln_kernel(const float* __restrict__ in, float* __restrict__ out,
                          const float* __restrict__ gam, const float* __restrict__ bet){
    int row = blockIdx.x;
    int t = threadIdx.x;
    const float4* x4 = (const float4*)(in + (size_t)row*D_);
    float4 v = x4[t];
    float s  = v.x+v.y+v.z+v.w;
    float s2 = v.x*v.x+v.y*v.y+v.z*v.z+v.w*v.w;
    #pragma unroll
    for (int o=16;o;o>>=1){ s += __shfl_xor_sync(0xffffffffu,s,o); s2 += __shfl_xor_sync(0xffffffffu,s2,o); }
    __shared__ float shs[8], shs2[8], bc[2];
    int w = t>>5, lane = t&31;
    if (!lane){ shs[w]=s; shs2[w]=s2; }
    __syncthreads();
    if (t==0){
        float ts=0.f, ts2=0.f;
        #pragma unroll
        for (int i=0;i<8;i++){ ts+=shs[i]; ts2+=shs2[i]; }
        float m   = ts*(1.0f/(float)D_);
        float var = ts2*(1.0f/(float)D_) - m*m;
        bc[0]=m; bc[1]=rsqrtf(var + 1e-5f);
    }
    __syncthreads();
    float m = bc[0], inv = bc[1];
    float4 gg = ((const float4*)gam)[t];
    float4 bb = ((const float4*)bet)[t];
    float4 o4;
    o4.x = (v.x-m)*inv*gg.x + bb.x;
    o4.y = (v.y-m)*inv*gg.y + bb.y;
    o4.z = (v.z-m)*inv*gg.z + bb.z;
    o4.w = (v.w-m)*inv*gg.w + bb.w;
    ((float4*)(out + (size_t)row*D_))[t] = o4;
}

// ================= tf32 tensor-core GEMM (unchanged from R2) ===============
#define TBM 128
#define TBN 128
#define TBK 16
#define ASTRIDE 20
#define BSTRIDE 136

template<int EPI>
__device__ __forceinline__ void tgemm_body(
    const float* __restrict__ A, const float* __restrict__ Bm,
    const float* __restrict__ bias, float* __restrict__ C,
    int N, int K)
{
    __shared__ uint32_t As[2][TBM][ASTRIDE];
    __shared__ uint32_t Bs[2][TBK][BSTRIDE];

    const int tid  = threadIdx.x;
    const int lane = tid & 31, wid = tid >> 5;
    const int wm = wid >> 1, wn = wid & 1;
    const int m0w = wm*32, n0w = wn*64;
    const int r = lane >> 2, cg = lane & 3;

    const int bm = blockIdx.y*TBM, bn = blockIdx.x*TBN;

    const int aRow0 = tid >> 2, aCg = tid & 3;
    const int bRow0 = tid >> 5, bCg = tid & 31;

    float acc[2][8][4];
    #pragma unroll
    for (int mt=0;mt<2;mt++)
        #pragma unroll
        for (int nt=0;nt<8;nt++)
            #pragma unroll
            for (int i=0;i<4;i++) acc[mt][nt][i]=0.f;

    const int nkt = K/TBK;

    {
        #pragma unroll
        for (int i=0;i<2;i++){
            int row = aRow0 + i*64;
            float4 v = *(const float4*)(A + (size_t)(bm+row)*K + aCg*4);
            uint4 t; t.x=f2tf(v.x); t.y=f2tf(v.y); t.z=f2tf(v.z); t.w=f2tf(v.w);
            *(uint4*)&As[0][row][aCg*4] = t;
        }
        #pragma unroll
        for (int i=0;i<2;i++){
            int row = bRow0 + i*8;
            float4 v = *(const float4*)(Bm + (size_t)row*N + bn + bCg*4);
            uint4 t; t.x=f2tf(v.x); t.y=f2tf(v.y); t.z=f2tf(v.z); t.w=f2tf(v.w);
            *(uint4*)&Bs[0][row][bCg*4] = t;
        }
    }
    __syncthreads();

    for (int kt=0; kt<nkt; kt++){
        const int cb = kt & 1, nb = cb ^ 1;
        const bool more = (kt+1 < nkt);
        float4 pa[2], pb[2];
        if (more){
            const int k0 = (kt+1)*TBK;
            #pragma unroll
            for (int i=0;i<2;i++){
                int row = aRow0 + i*64;
                pa[i] = *(const float4*)(A + (size_t)(bm+row)*K + k0 + aCg*4);
            }
            #pragma unroll
            for (int i=0;i<2;i++){
                int row = bRow0 + i*8;
                pb[i] = *(const float4*)(Bm + (size_t)(k0+row)*N + bn + bCg*4);
            }
        }

        #pragma unroll
        for (int ks=0; ks<2; ks++){
            uint32_t af[2][4];
            #pragma unroll
            for (int mt=0;mt<2;mt++){
                int mb = m0w + mt*16 + r;
                af[mt][0] = As[cb][mb   ][ks*8 + cg    ];
                af[mt][1] = As[cb][mb+8 ][ks*8 + cg    ];
                af[mt][2] = As[cb][mb   ][ks*8 + cg + 4];
                af[mt][3] = As[cb][mb+8 ][ks*8 + cg + 4];
            }
            uint32_t bf[8][2];
            #pragma unroll
            for (int nt=0;nt<8;nt++){
                bf[nt][0] = Bs[cb][ks*8 + cg    ][n0w + nt*8 + r];
                bf[nt][1] = Bs[cb][ks*8 + cg + 4][n0w + nt*8 + r];
            }
            #pragma unroll
            for (int mt=0;mt<2;mt++)
                #pragma unroll
                for (int nt=0;nt<8;nt++)
                    mma_tf32(acc[mt][nt], af[mt], bf[nt]);
        }

        if (more){
            #pragma unroll
            for (int i=0;i<2;i++){
                int row = aRow0 + i*64;
                uint4 t; t.x=f2tf(pa[i].x); t.y=f2tf(pa[i].y); t.z=f2tf(pa[i].z); t.w=f2tf(pa[i].w);
                *(uint4*)&As[nb][row][aCg*4] = t;
            }
            #pragma unroll
            for (int i=0;i<2;i++){
                int row = bRow0 + i*8;
                uint4 t; t.x=f2tf(pb[i].x); t.y=f2tf(pb[i].y); t.z=f2tf(pb[i].z); t.w=f2tf(pb[i].w);
                *(uint4*)&Bs[nb][row][bCg*4] = t;
            }
        }
        __syncthreads();
    }

    #pragma unroll
    for (int mt=0;mt<2;mt++){
        int row0 = bm + m0w + mt*16 + r;
        #pragma unroll
        for (int nt=0;nt<8;nt++){
            int col = bn + n0w + nt*8 + cg*2;
            float2 b2 = make_float2(0.f,0.f);
            if (EPI >= 1) b2 = *(const float2*)(bias + col);
            float2 v0, v1;
            v0.x = acc[mt][nt][0] + b2.x; v0.y = acc[mt][nt][1] + b2.y;
            v1.x = acc[mt][nt][2] + b2.x; v1.y = acc[mt][nt][3] + b2.y;
            if (EPI == 2){
                v0.x = gelu_t(v0.x); v0.y = gelu_t(v0.y);
                v1.x = gelu_t(v1.x); v1.y = gelu_t(v1.y);
            }
            *(float2*)(C + (size_t)row0*N + col)     = v0;
            *(float2*)(C + (size_t)(row0+8)*N + col) = v1;
        }
    }
}

template<int EPI>
__global__ void __launch_bounds__(256)
tgemm_kernel(const float* __restrict__ A, const float* __restrict__ Bm,
             const float* __restrict__ bias, float* __restrict__ C, int N, int K)
{
    tgemm_body<EPI>(A, Bm, bias, C, N, K);
}

__global__ void __launch_bounds__(256)
qkvr_kernel(const float* __restrict__ xn, const float* __restrict__ rel,
            const float* __restrict__ Wq, const float* __restrict__ Wk,
            const float* __restrict__ Wv, const float* __restrict__ Wr,
            float* __restrict__ q, float* __restrict__ k,
            float* __restrict__ v, float* __restrict__ rr)
{
    const int z = blockIdx.z;
    if (z == 3 && blockIdx.y*TBM >= S_) return;
    const float* A = (z < 3) ? xn : rel;
    const float* W = (z==0) ? Wq : (z==1) ? Wk : (z==2) ? Wv : Wr;
    float*       C = (z==0) ? q  : (z==1) ? k  : (z==2) ? v  : rr;
    tgemm_body<0>(A, W, nullptr, C, D_, D_);
}

// ---------------- bias precompute: uk[b,h,key]=u·k, vr[h,row]=v·r ----------
__global__ void bias_kernel(const float* __restrict__ uvec, const float* __restrict__ vvec){
    const int t = threadIdx.x;
    if (blockIdx.y == 0){
        int row = blockIdx.x;                 // b*S + key
        float4 kv = ((const float4*)(g_k + (size_t)row*D_))[t];
        float4 uu = ((const float4*)uvec)[t];
        float p = kv.x*uu.x + kv.y*uu.y + kv.z*uu.z + kv.w*uu.w;
        p += __shfl_xor_sync(0xffffffffu, p, 8);
        p += __shfl_xor_sync(0xffffffffu, p, 4);
        p += __shfl_xor_sync(0xffffffffu, p, 2);
        p += __shfl_xor_sync(0xffffffffu, p, 1);
        if ((t & 15) == 0){
            int h = t >> 4;
            int b = row >> 10, key = row & (S_-1);
            g_uk[((size_t)(b*H_ + h))*S_ + key] = p;
        }
    } else {
        int rrow = blockIdx.x;
        if (rrow >= S_) return;
        float4 rv = ((const float4*)(g_r + (size_t)rrow*D_))[t];
        float4 vv = ((const float4*)vvec)[t];
        float p = rv.x*vv.x + rv.y*vv.y + rv.z*vv.z + rv.w*vv.w;
        p += __shfl_xor_sync(0xffffffffu, p, 8);
        p += __shfl_xor_sync(0xffffffffu, p, 4);
        p += __shfl_xor_sync(0xffffffffu, p, 2);
        p += __shfl_xor_sync(0xffffffffu, p, 1);
        if ((t & 15) == 0)
            g_vr[(t>>4)*S_ + rrow] = p;
    }
}

// ---------------- tensor-core score kernel ---------------------------------
// scores[b,h,q,k] = 0.125*( Q·K^T + uk[k] + C2[q, 63+k-q] + vr[S-1-q+k] ), k<=q
// C2 = Q @ Rband^T.  Dynamic smem: Qs[64][68] Ks[64(d)][72] Rs[64(d)][136] C2[64][132]
#define QSS 68
#define KSS 72
#define RSS 136
#define CSS 132
#define SC_SMEM ((64*QSS + 64*KSS + 64*RSS + 64*CSS)*4)

__global__ void __launch_bounds__(256)
score_kernel(){
    if (blockIdx.x > blockIdx.y) return;
    const int kt0 = blockIdx.x*64, qt0 = blockIdx.y*64;
    const int bh = blockIdx.z, b = bh >> 4, h = bh & 15;
    const int rbase = S_ - 64 - qt0 + kt0;

    extern __shared__ uint32_t sm[];
    uint32_t* Qs = sm;                  // [64][QSS]  A operand (q rows, d cols)
    uint32_t* Ks = Qs + 64*QSS;         // [64][KSS]  [d][key]
    uint32_t* Rs = Ks + 64*KSS;         // [64][RSS]  [d][j], j in 0..127
    float*    C2 = (float*)(Rs + 64*RSS); // [64][CSS]

    const int tid = threadIdx.x;
    const int lane = tid & 31, wid = tid >> 5;
    const int wm = wid >> 1, wn = wid & 1;
    const int r = lane >> 2, cg = lane & 3;

    // ---- fill Qs (row-major) and Ks (transposed)
    {
        const int pos = tid & 63, dg = tid >> 6;   // dg: 0..3 -> d chunk of 16
        const float* qrow = g_q + ((size_t)(b*S_ + qt0 + pos))*D_ + h*DH_;
        const float* krow = g_k + ((size_t)(b*S_ + kt0 + pos))*D_ + h*DH_;
        #pragma unroll
        for (int c=0;c<4;c++){
            int d0 = dg*16 + c*4;
            float4 v = *(const float4*)(qrow + d0);
            uint4 t; t.x=f2tf(v.x); t.y=f2tf(v.y); t.z=f2tf(v.z); t.w=f2tf(v.w);
            *(uint4*)&Qs[pos*QSS + d0] = t;
            float4 w = *(const float4*)(krow + d0);
            Ks[(d0+0)*KSS + pos] = f2tf(w.x);
            Ks[(d0+1)*KSS + pos] = f2tf(w.y);
            Ks[(d0+2)*KSS + pos] = f2tf(w.z);
            Ks[(d0+3)*KSS + pos] = f2tf(w.w);
        }
    }
    // ---- fill Rs (transposed), 128 j-columns
    {
        const int j = tid & 127, dh2 = tid >> 7;   // dh2: 0..1 -> d chunk of 32
        const int rrow = rbase + j;
        if (rrow >= 0 && rrow < S_ && j < 127){
            const float* rr = g_r + (size_t)rrow*D_ + h*DH_ + dh2*32;
            #pragma unroll
            for (int c=0;c<8;c++){
                float4 v = *(const float4*)(rr + c*4);
                int d0 = dh2*32 + c*4;
                Rs[(d0+0)*RSS + j] = f2tf(v.x);
                Rs[(d0+1)*RSS + j] = f2tf(v.y);
                Rs[(d0+2)*RSS + j] = f2tf(v.z);
                Rs[(d0+3)*RSS + j] = f2tf(v.w);
            }
        } else {
            #pragma unroll
            for (int c=0;c<8;c++){
                int d0 = dh2*32 + c*4;
                Rs[(d0+0)*RSS + j] = 0u;
                Rs[(d0+1)*RSS + j] = 0u;
                Rs[(d0+2)*RSS + j] = 0u;
                Rs[(d0+3)*RSS + j] = 0u;
            }
        }
    }
    __syncthreads();

    // ---- mma: AC (n=64 split over wn*32) and C2 (n=128 split over wn*64)
    float accA[4][4]; float accB[8][4];
    #pragma unroll
    for (int nt=0;nt<4;nt++){ accA[nt][0]=accA[nt][1]=accA[nt][2]=accA[nt][3]=0.f; }
    #pragma unroll
    for (int nt=0;nt<8;nt++){ accB[nt][0]=accB[nt][1]=accB[nt][2]=accB[nt][3]=0.f; }

    #pragma unroll
    for (int ks=0; ks<8; ks++){
        uint32_t a[4];
        const int mr = wm*16 + r;
        a[0] = Qs[mr*QSS     + ks*8 + cg];
        a[1] = Qs[(mr+8)*QSS + ks*8 + cg];
        a[2] = Qs[mr*QSS     + ks*8 + cg + 4];
        a[3] = Qs[(mr+8)*QSS + ks*8 + cg + 4];
        #pragma unroll
        for (int nt=0;nt<4;nt++){
            uint32_t bfr[2];
            bfr[0] = Ks[(ks*8+cg  )*KSS + wn*32 + nt*8 + r];
            bfr[1] = Ks[(ks*8+cg+4)*KSS + wn*32 + nt*8 + r];
            mma_tf32(accA[nt], a, bfr);
        }
        #pragma unroll
        for (int nt=0;nt<8;nt++){
            uint32_t bfr[2];
            bfr[0] = Rs[(ks*8+cg  )*RSS + wn*64 + nt*8 + r];
            bfr[1] = Rs[(ks*8+cg+4)*RSS + wn*64 + nt*8 + r];
            mma_tf32(accB[nt], a, bfr);
        }
    }
    // stage C2 to smem
    #pragma unroll
    for (int nt=0;nt<8;nt++){
        int col = wn*64 + nt*8 + cg*2;
        C2[(wm*16+r  )*CSS + col    ] = accB[nt][0];
        C2[(wm*16+r  )*CSS + col + 1] = accB[nt][1];
        C2[(wm*16+r+8)*CSS + col    ] = accB[nt][2];
        C2[(wm*16+r+8)*CSS + col + 1] = accB[nt][3];
    }
    __syncthreads();

    // ---- epilogue: combine, mask, write
    const float* ukp = g_uk + (size_t)bh*S_ + kt0;
    const float* vrp = g_vr + (size_t)h*S_;
    #pragma unroll
    for (int i=0;i<2;i++){
        const int qr = wm*16 + r + i*8;
        const int q  = qt0 + qr;
        #pragma unroll
        for (int nt=0;nt<4;nt++){
            const int kr0 = wn*32 + nt*8 + cg*2;
            float2 o2;
            #pragma unroll
            for (int cc=0;cc<2;cc++){
                const int kr = kr0 + cc;
                const int k  = kt0 + kr;
                float sc;
                if (k <= q){
                    float bd = C2[qr*CSS + 63 + kr - qr] + vrp[S_-1-q+k];
                    sc = (accA[nt][i*2+cc] + ukp[kr] + bd) * 0.125f;
                } else sc = -1e30f;
                (cc ? o2.y : o2.x) = sc;
            }
            *(float2*)(g_aw + ((size_t)bh*S_ + q)*S_ + kt0 + kr0) = o2;
        }
    }
}

// ---------------- softmax per row -------------------------------------------
__global__ void softmax_kernel(const int* __restrict__ text){
    const int q = blockIdx.x, bh = blockIdx.y, b = bh >> 4;
    float* row = g_aw + ((size_t)bh*S_ + q)*S_;
    const int t = threadIdx.x;
    float4 v = ((float4*)row)[t];
    const int k0 = t*4;
    float vals[4] = {v.x, v.y, v.z, v.w};
    float mx = -1e30f;
    #pragma unroll
    for (int c=0;c<4;c++) if (k0+c <= q) mx = fmaxf(mx, vals[c]);
    #pragma unroll
    for (int o=16;o;o>>=1) mx = fmaxf(mx, __shfl_xor_sync(0xffffffffu, mx, o));
    __shared__ float sh[8], bc[2];
    int w = t>>5, lane = t&31;
    if (!lane) sh[w] = mx;
    __syncthreads();
    if (t==0){ float m=sh[0]; for (int i=1;i<8;i++) m=fmaxf(m,sh[i]); bc[0]=m; }
    __syncthreads();
    mx = bc[0];
    float e[4]; float s = 0.f;
    #pragma unroll
    for (int c=0;c<4;c++){ e[c] = (k0+c <= q) ? __expf(vals[c]-mx) : 0.f; s += e[c]; }
    #pragma unroll
    for (int o=16;o;o>>=1) s += __shfl_xor_sync(0xffffffffu, s, o);
    if (!lane) sh[w] = s;
    __syncthreads();
    if (t==0){ float m=0.f; for (int i=0;i<8;i++) m+=sh[i]; bc[1]=m; }
    __syncthreads();
    bool padq = (text[b*CTX_ + q] == PAD_);
    float inv = padq ? 0.f : 1.0f/bc[1];
    v.x=e[0]*inv; v.y=e[1]*inv; v.z=e[2]*inv; v.w=e[3]*inv;
    ((float4*)row)[t] = v;
}

// ---------------- tensor-core o = aw @ v ------------------------------------
#define AWS 68
#define VSS 72
__global__ void __launch_bounds__(256)
av2_kernel(){
    const int qt0 = blockIdx.x*64;
    const int bh = blockIdx.y, b = bh>>4, h = bh&15;
    __shared__ uint32_t AWs[64*AWS];
    __shared__ uint32_t Vs [64*VSS];

    const int tid = threadIdx.x;
    const int lane = tid & 31, wid = tid >> 5;
    const int wm = wid >> 1, wn = wid & 1;
    const int r = lane >> 2, cg = lane & 3;
    const int pos = tid & 63, dg = tid >> 6;

    float acc[4][4];
    #pragma unroll
    for (int nt=0;nt<4;nt++){ acc[nt][0]=acc[nt][1]=acc[nt][2]=acc[nt][3]=0.f; }

    for (int kt=0; kt<=blockIdx.x; kt++){
        {
            const float* arow = g_aw + ((size_t)bh*S_ + qt0 + pos)*S_ + kt*64;
            const float* vrow = g_v  + ((size_t)(b*S_ + kt*64 + pos))*D_ + h*DH_;
            #pragma unroll
            for (int c=0;c<4;c++){
                int d0 = dg*16 + c*4;
                float4 v = *(const float4*)(arow + d0);
                uint4 t; t.x=f2tf(v.x); t.y=f2tf(v.y); t.z=f2tf(v.z); t.w=f2tf(v.w);
                *(uint4*)&AWs[pos*AWS + d0] = t;
                float4 w = *(const float4*)(vrow + d0);
                uint4 tw; tw.x=f2tf(w.x); tw.y=f2tf(w.y); tw.z=f2tf(w.z); tw.w=f2tf(w.w);
                *(uint4*)&Vs[pos*VSS + d0] = tw;
            }
        }
        __syncthreads();
        #pragma unroll
        for (int ks=0; ks<8; ks++){
            uint32_t a[4];
            const int mr = wm*16 + r;
            a[0] = AWs[mr*AWS     + ks*8 + cg];
            a[1] = AWs[(mr+8)*AWS + ks*8 + cg];
            a[2] = AWs[mr*AWS     + ks*8 + cg + 4];
            a[3] = AWs[(mr+8)*AWS + ks*8 + cg + 4];
            #pragma unroll
            for (int nt=0;nt<4;nt++){
                uint32_t bfr[2];
                bfr[0] = Vs[(ks*8+cg  )*VSS + wn*32 + nt*8 + r];
                bfr[1] = Vs[(ks*8+cg+4)*VSS + wn*32 + nt*8 + r];
                mma_tf32(acc[nt], a, bfr);
            }
        }
        __syncthreads();
    }
    #pragma unroll
    for (int i=0;i<2;i++){
        int q = qt0 + wm*16 + r + i*8;
        #pragma unroll
        for (int nt=0;nt<4;nt++){
            float2 o2;
            o2.x = acc[nt][i*2+0]; o2.y = acc[nt][i*2+1];
            *(float2*)(g_o + ((size_t)(b*S_ + q))*D_ + h*DH_ + wn*32 + nt*8 + cg*2) = o2;
        }
    }
}

// ---------------- residual fusions -----------------------------------------
__global__ void resid_attn_kernel(const float* __restrict__ bfc){
    int idx = blockIdx.x*256 + threadIdx.x;
    int d4 = idx & (D_/4 - 1);
    float4 x  = ((float4*)g_x)[idx];
    float4 t  = ((const float4*)g_tmp)[idx];
    float4 xn = ((const float4*)g_xn)[idx];
    float4 bb = ((const float4*)bfc)[d4];
    x.x += t.x + xn.x + bb.x;
    x.y += t.y + xn.y + bb.y;
    x.z += t.z + xn.z + bb.z;
    x.w += t.w + xn.w + bb.w;
    ((float4*)g_x)[idx] = x;
}

__global__ void resid_add_kernel(){
    int idx = blockIdx.x*256 + threadIdx.x;
    float4 x = ((float4*)g_x)[idx];
    float4 t = ((const float4*)g_tmp)[idx];
    x.x+=t.x; x.y+=t.y; x.z+=t.z; x.w+=t.w;
    ((float4*)g_x)[idx] = x;
}

// ---------------- orchestration ---------------------------------------------
extern "C" void kernel_launch(void* const* d_in, const int* in_sizes, int n_in,
                              void* d_out, int out_size)
{
    (void)in_sizes; (void)n_in; (void)out_size;
    const int*   text = (const int*)  d_in[0];
    const float* emb  = (const float*)d_in[1];
    const float* u    = (const float*)d_in[2];
    const float* vbp  = (const float*)d_in[3];
    const float* Wq   = (const float*)d_in[4];
    const float* Wk   = (const float*)d_in[5];
    const float* Wv   = (const float*)d_in[6];
    const float* Wr   = (const float*)d_in[7];
    const float* Wfc  = (const float*)d_in[8];
    const float* bfc  = (const float*)d_in[9];
    const float* ln1g = (const float*)d_in[10];
    const float* ln1b = (const float*)d_in[11];
    const float* ln2g = (const float*)d_in[12];
    const float* ln2b = (const float*)d_in[13];
    const float* W1   = (const float*)d_in[14];
    const float* b1   = (const float*)d_in[15];
    const float* W2   = (const float*)d_in[16];
    const float* b2   = (const float*)d_in[17];
    const float* lnfg = (const float*)d_in[18];
    const float* lnfb = (const float*)d_in[19];
    const float* Wlm  = (const float*)d_in[20];
    const float* blm  = (const float*)d_in[21];
    float* out = (float*)d_out;

    float *px,*pxn,*pq,*pk,*pv,*po,*ptmp,*prel,*pr,*pff;
    cudaGetSymbolAddress((void**)&px,   g_x);
    cudaGetSymbolAddress((void**)&pxn,  g_xn);
    cudaGetSymbolAddress((void**)&pq,   g_q);
    cudaGetSymbolAddress((void**)&pk,   g_k);
    cudaGetSymbolAddress((void**)&pv,   g_v);
    cudaGetSymbolAddress((void**)&po,   g_o);
    cudaGetSymbolAddress((void**)&ptmp, g_tmp);
    cudaGetSymbolAddress((void**)&prel, g_rel);
    cudaGetSymbolAddress((void**)&pr,   g_r);
    cudaGetSymbolAddress((void**)&pff,  g_ff);

    static bool attr_done = false;
    if (!attr_done){
        cudaFuncSetAttribute(score_kernel, cudaFuncAttributeMaxDynamicSharedMemorySize, SC_SMEM);
        attr_done = true;
    }

    const int MR = B_*S_;

    embed_kernel<<<2048,256>>>(text, emb);
    rel_kernel  <<<2048,256>>>();

    for (int l=0; l<L_; l++){
        ln_kernel<<<MR,256>>>(px, pxn, ln1g + l*D_, ln1b + l*D_);

        qkvr_kernel<<<dim3(D_/TBN, MR/TBM, 4),256>>>(
            pxn, prel,
            Wq + (size_t)l*D_*D_, Wk + (size_t)l*D_*D_,
            Wv + (size_t)l*D_*D_, Wr + (size_t)l*D_*D_,
            pq, pk, pv, pr);

        bias_kernel   <<<dim3(B_*S_, 2),256>>>(u, vbp);
        score_kernel  <<<dim3(16,16,B_*H_),256, SC_SMEM>>>();
        softmax_kernel<<<dim3(S_, B_*H_),256>>>(text);
        av2_kernel    <<<dim3(16, B_*H_),256>>>();

        tgemm_kernel<0><<<dim3(D_/TBN, MR/TBM),256>>>(po, Wfc + (size_t)l*D_*D_, nullptr, ptmp, D_, D_);
        resid_attn_kernel<<<2048,256>>>(bfc + l*D_);

        ln_kernel<<<MR,256>>>(px, pxn, ln2g + l*D_, ln2b + l*D_);
        tgemm_kernel<2><<<dim3(FF_/TBN, MR/TBM),256>>>(pxn, W1 + (size_t)l*D_*FF_, b1 + l*FF_, pff, FF_, D_);
        tgemm_kernel<2><<<dim3(D_/TBN, MR/TBM),256>>>(pff, W2 + (size_t)l*FF_*D_, b2 + l*D_, ptmp, D_, FF_);
        resid_add_kernel<<<2048,256>>>();
    }

    ln_kernel<<<MR,256>>>(px, pxn, lnfg, lnfb);
    tgemm_kernel<1><<<dim3(V_/TBN, MR/TBM),256>>>(pxn, Wlm, blm, out, V_, D_);
}